// round 4
// baseline (speedup 1.0000x reference)
#include <cuda_runtime.h>

// PEquiNN: o_x = l_xx*X + (g_xx*rowsum(X) + g_yx*rowsum(Y)) per row
//          o_y = l_yy*Y + (g_yy*rowsum(Y) + g_xy*rowsum(X)) per row
// X, Y: [8192, 4096] f32. Single-pass streaming: 256 MiB read + 256 MiB write
// (provably minimal traffic). Measured binding constraint: DRAM efficiency
// under 1:1 read/write mix (~6.3 TB/s of 8 TB/s spec).
//
// R3: R1 layout (best measured DRAM%): 256 threads, one row per CTA, full
// row pair held in registers across the joint reduction. Single change vs
// R1: __ldcs on input loads (read-once data -> evict-first, keeps L2 ways
// free for dirty output lines so writebacks batch better). Stores stay
// default (evict-normal) -- R2 showed __stcs stores lowered DRAM%.

#define N_COLS 4096
#define VEC_PER_ROW (N_COLS / 4)   // 1024 float4 per row
#define THREADS 256
#define V_PER_THREAD (VEC_PER_ROW / THREADS)  // 4 float4 = 16 floats per thread

__global__ __launch_bounds__(THREADS)
void peq_kernel(const float4* __restrict__ X,
                const float4* __restrict__ Y,
                const float* __restrict__ p_lxx,
                const float* __restrict__ p_lyy,
                const float* __restrict__ p_gxx,
                const float* __restrict__ p_gxy,
                const float* __restrict__ p_gyx,
                const float* __restrict__ p_gyy,
                float4* __restrict__ OX,
                float4* __restrict__ OY)
{
    const int row = blockIdx.x;
    const size_t base = (size_t)row * VEC_PER_ROW;
    const int tid = threadIdx.x;

    // Load the full row (X and Y) into registers; accumulate partial sums.
    float4 xv[V_PER_THREAD];
    float4 yv[V_PER_THREAD];
    float sx = 0.f, sy = 0.f;
#pragma unroll
    for (int i = 0; i < V_PER_THREAD; i++) {
        xv[i] = __ldcs(&X[base + tid + i * THREADS]);
        yv[i] = __ldcs(&Y[base + tid + i * THREADS]);
        sx += (xv[i].x + xv[i].y) + (xv[i].z + xv[i].w);
        sy += (yv[i].x + yv[i].y) + (yv[i].z + yv[i].w);
    }

    // Warp reduce both sums.
#pragma unroll
    for (int o = 16; o > 0; o >>= 1) {
        sx += __shfl_xor_sync(0xFFFFFFFFu, sx, o);
        sy += __shfl_xor_sync(0xFFFFFFFFu, sy, o);
    }

    // Cross-warp reduce (8 warps).
    __shared__ float ssx[THREADS / 32];
    __shared__ float ssy[THREADS / 32];
    const int wid = tid >> 5;
    const int lid = tid & 31;
    if (lid == 0) { ssx[wid] = sx; ssy[wid] = sy; }
    __syncthreads();
    sx = 0.f; sy = 0.f;
#pragma unroll
    for (int i = 0; i < THREADS / 32; i++) { sx += ssx[i]; sy += ssy[i]; }

    // Scalars (uniform loads, cached after first CTA).
    const float lxx = __ldg(p_lxx);
    const float lyy = __ldg(p_lyy);
    const float gxx = __ldg(p_gxx);
    const float gxy = __ldg(p_gxy);
    const float gyx = __ldg(p_gyx);
    const float gyy = __ldg(p_gyy);

    const float bx = gxx * sx + gyx * sy;  // broadcast term for o_x row
    const float by = gyy * sy + gxy * sx;  // broadcast term for o_y row

#pragma unroll
    for (int i = 0; i < V_PER_THREAD; i++) {
        float4 ox, oy;
        ox.x = fmaf(lxx, xv[i].x, bx);
        ox.y = fmaf(lxx, xv[i].y, bx);
        ox.z = fmaf(lxx, xv[i].z, bx);
        ox.w = fmaf(lxx, xv[i].w, bx);
        oy.x = fmaf(lyy, yv[i].x, by);
        oy.y = fmaf(lyy, yv[i].y, by);
        oy.z = fmaf(lyy, yv[i].z, by);
        oy.w = fmaf(lyy, yv[i].w, by);
        OX[base + tid + i * THREADS] = ox;
        OY[base + tid + i * THREADS] = oy;
    }
}

extern "C" void kernel_launch(void* const* d_in, const int* in_sizes, int n_in,
                              void* d_out, int out_size)
{
    const float4* X = (const float4*)d_in[0];
    const float4* Y = (const float4*)d_in[1];
    const float* lxx = (const float*)d_in[2];
    const float* lyy = (const float*)d_in[3];
    const float* gxx = (const float*)d_in[4];
    const float* gxy = (const float*)d_in[5];
    const float* gyx = (const float*)d_in[6];
    const float* gyy = (const float*)d_in[7];

    const int total = in_sizes[0];          // R * N = 8192 * 4096
    const int rows = total / N_COLS;        // 8192

    float* out = (float*)d_out;
    float4* OX = (float4*)out;                          // o_x first
    float4* OY = (float4*)(out + (size_t)total);        // o_y second

    peq_kernel<<<rows, THREADS>>>(X, Y, lxx, lyy, gxx, gxy, gyx, gyy, OX, OY);
}